// round 14
// baseline (speedup 1.0000x reference)
#include <cuda_runtime.h>
#include <cuda_fp16.h>

#define NN 50000
#define NE 800000
#define NG 256
#define F  64
#define CAP 32                 // per-shard capacity (Poisson(4) tail ~1e-18)
#define ROWSTRIDE 128          // 4 shards * CAP

// ---------------- scratch ----------------
__device__ __align__(16) __half g_hh[NN * F];     // h * dinv[src], fp16
__device__ __align__(16) float g_agg[NN * F];     // self-loop init, then full agg
__device__ __align__(16) float g_sums[NG * F];
__device__ float g_cnt[NG];
__device__ __align__(16) int g_cursor4[NN * 4];   // sharded cursors == shard degrees
__device__ int g_ssorted[NN * ROWSTRIDE];         // padded CSR (src indices)

__device__ __forceinline__ void red_add_v4(float* p, float4 v) {
    asm volatile("red.global.add.v4.f32 [%0], {%1, %2, %3, %4};"
                 :: "l"(p), "f"(v.x), "f"(v.y), "f"(v.z), "f"(v.w) : "memory");
}

__device__ __forceinline__ void node_scales(int node, float& dv, float& id) {
    int4 c = ((const int4*)g_cursor4)[node];
    float d = (float)(c.x + c.y + c.z + c.w + 1);
    dv = rsqrtf(d);
    id = 1.0f / d;
}

// ---------------- prep ----------------
__global__ void zero_kernel() {
    int i = blockIdx.x * blockDim.x + threadIdx.x;
    if (i < NG * F) g_sums[i] = 0.0f;
    if (i < NG) g_cnt[i] = 0.0f;
}

// direct padded-CSR scatter: no deg pass, no scan
__global__ void scatter_kernel(const int* __restrict__ src, const int* __restrict__ dst) {
    int e = blockIdx.x * blockDim.x + threadIdx.x;
    if (e < NE) {
        int d = dst[e];
        int sh = e & 3;
        int pos = atomicAdd(&g_cursor4[d * 4 + sh], 1);
        if (pos < CAP) g_ssorted[d * ROWSTRIDE + sh * CAP + pos] = src[e];
    }
}

// ---------------- Tensor-core GEMM + self-loop init ----------------
// in = (FIRST ? x : relu(g_agg + b_prev)); a = in @ W (fp16 in, fp32 accum)
// g_hh = half(a * dinv); g_agg = a * invdeg   (dinv/invdeg inline from cursors)
#define XS_STRIDE 66

template <bool FIRST>
__global__ __launch_bounds__(128) void gemm_tc_kernel(const float* __restrict__ x,
                                                      const float* __restrict__ W,
                                                      const float* __restrict__ bprev) {
    __shared__ __half Wt[F * XS_STRIDE];        // Wt[n][k] = W[k][n]
    __shared__ __half Xs[4][16 * XS_STRIDE];

    int tid = threadIdx.x;
    for (int i = tid; i < F * F; i += 128) {
        int k = i >> 6, n = i & 63;
        Wt[n * XS_STRIDE + k] = __float2half(W[i]);
    }

    int warp = tid >> 5, lane = tid & 31;
    int gid = lane >> 2, tig = lane & 3;
    int nodebase = blockIdx.x * 64 + warp * 16;

    const float4* in4 = FIRST ? (const float4*)x : (const float4*)g_agg;
    const float4* b4 = (const float4*)bprev;
    int hl = lane >> 4;
    int qi = lane & 15;
    __half* Xw = Xs[warp];
#pragma unroll
    for (int rr = 0; rr < 8; ++rr) {
        int r = rr * 2 + hl;
        int node = nodebase + r;
        float4 xv = make_float4(0.f, 0.f, 0.f, 0.f);
        if (node < NN) {
            xv = in4[(size_t)node * 16 + qi];
            if (!FIRST) {
                float4 bv = b4[qi];
                xv.x = fmaxf(xv.x + bv.x, 0.f);
                xv.y = fmaxf(xv.y + bv.y, 0.f);
                xv.z = fmaxf(xv.z + bv.z, 0.f);
                xv.w = fmaxf(xv.w + bv.w, 0.f);
            }
        }
        __half2* p = (__half2*)&Xw[r * XS_STRIDE + qi * 4];
        p[0] = __floats2half2_rn(xv.x, xv.y);
        p[1] = __floats2half2_rn(xv.z, xv.w);
    }
    __syncthreads();

    unsigned a[4][4];
#pragma unroll
    for (int kt = 0; kt < 4; ++kt) {
        int kc = kt * 16 + tig * 2;
        a[kt][0] = *(const unsigned*)&Xw[gid * XS_STRIDE + kc];
        a[kt][1] = *(const unsigned*)&Xw[(gid + 8) * XS_STRIDE + kc];
        a[kt][2] = *(const unsigned*)&Xw[gid * XS_STRIDE + kc + 8];
        a[kt][3] = *(const unsigned*)&Xw[(gid + 8) * XS_STRIDE + kc + 8];
    }

    int row0 = nodebase + gid;
    int row1 = nodebase + gid + 8;
    float dv0 = 0.f, id0 = 0.f, dv1 = 0.f, id1 = 0.f;
    if (row0 < NN) node_scales(row0, dv0, id0);
    if (row1 < NN) node_scales(row1, dv1, id1);

#pragma unroll
    for (int nt = 0; nt < 8; ++nt) {
        float c0 = 0.f, c1 = 0.f, c2 = 0.f, c3 = 0.f;
        const __half* Wn = &Wt[(nt * 8 + gid) * XS_STRIDE];
#pragma unroll
        for (int kt = 0; kt < 4; ++kt) {
            int kc = kt * 16 + tig * 2;
            unsigned b0 = *(const unsigned*)&Wn[kc];
            unsigned b1 = *(const unsigned*)&Wn[kc + 8];
            asm volatile(
                "mma.sync.aligned.m16n8k16.row.col.f32.f16.f16.f32 "
                "{%0,%1,%2,%3}, {%4,%5,%6,%7}, {%8,%9}, {%0,%1,%2,%3};"
                : "+f"(c0), "+f"(c1), "+f"(c2), "+f"(c3)
                : "r"(a[kt][0]), "r"(a[kt][1]), "r"(a[kt][2]), "r"(a[kt][3]),
                  "r"(b0), "r"(b1));
        }
        int col = nt * 8 + tig * 2;
        if (row0 < NN) {
            *(__half2*)&g_hh[(size_t)row0 * F + col] = __floats2half2_rn(c0 * dv0, c1 * dv0);
            *(float2*)&g_agg[(size_t)row0 * F + col] = make_float2(c0 * id0, c1 * id0);
        }
        if (row1 < NN) {
            *(__half2*)&g_hh[(size_t)row1 * F + col] = __floats2half2_rn(c2 * dv1, c3 * dv1);
            *(float2*)&g_agg[(size_t)row1 * F + col] = make_float2(c2 * id1, c3 * id1);
        }
    }
}

// ---------------- padded-CSR aggregation: 8-lane group per dst ----------------
// g_agg[d] = self_term + dinv[d] * sum_{shards} sum g_hh[s]
// LAST: pool relu(out + b3) into g_sums + count nodes per graph.
template <bool LAST>
__global__ __launch_bounds__(256) void agg_kernel(const int* __restrict__ batch,
                                                  const float* __restrict__ b3) {
    int t = blockIdx.x * blockDim.x + threadIdx.x;
    int d = t >> 3;
    int l = t & 7;
    if (d >= NN) return;

    int4 shv = ((const int4*)g_cursor4)[d];
    int shn[4] = {shv.x, shv.y, shv.z, shv.w};
    float dfl = (float)(shn[0] + shn[1] + shn[2] + shn[3] + 1);
    float dd = rsqrtf(dfl);

    const uint4* h4 = (const uint4*)g_hh;
    float acc[8];
#pragma unroll
    for (int j = 0; j < 8; ++j) acc[j] = 0.f;

#pragma unroll
    for (int s = 0; s < 4; ++s) {
        int n = shn[s];
        if (n > CAP) n = CAP;
        int start = d * ROWSTRIDE + s * CAP;
        int i = 0;
        for (; i + 4 <= n; i += 4) {
            int s0 = g_ssorted[start + i];
            int s1 = g_ssorted[start + i + 1];
            int s2 = g_ssorted[start + i + 2];
            int s3 = g_ssorted[start + i + 3];
            uint4 r0 = h4[(size_t)s0 * 8 + l];
            uint4 r1 = h4[(size_t)s1 * 8 + l];
            uint4 r2 = h4[(size_t)s2 * 8 + l];
            uint4 r3 = h4[(size_t)s3 * 8 + l];
            const __half2* p0 = (const __half2*)&r0;
            const __half2* p1 = (const __half2*)&r1;
            const __half2* p2 = (const __half2*)&r2;
            const __half2* p3 = (const __half2*)&r3;
#pragma unroll
            for (int j = 0; j < 4; ++j) {
                float2 f0 = __half22float2(p0[j]);
                float2 f1 = __half22float2(p1[j]);
                float2 f2 = __half22float2(p2[j]);
                float2 f3 = __half22float2(p3[j]);
                acc[j * 2 + 0] += (f0.x + f1.x) + (f2.x + f3.x);
                acc[j * 2 + 1] += (f0.y + f1.y) + (f2.y + f3.y);
            }
        }
        for (; i < n; ++i) {
            int s0 = g_ssorted[start + i];
            uint4 r0 = h4[(size_t)s0 * 8 + l];
            const __half2* p0 = (const __half2*)&r0;
#pragma unroll
            for (int j = 0; j < 4; ++j) {
                float2 f0 = __half22float2(p0[j]);
                acc[j * 2 + 0] += f0.x;
                acc[j * 2 + 1] += f0.y;
            }
        }
    }

    float4* ar = (float4*)(g_agg + (size_t)d * F + l * 8);
    float4 s0v = ar[0];
    float4 s1v = ar[1];
    float4 o0 = make_float4(fmaf(acc[0], dd, s0v.x), fmaf(acc[1], dd, s0v.y),
                            fmaf(acc[2], dd, s0v.z), fmaf(acc[3], dd, s0v.w));
    float4 o1 = make_float4(fmaf(acc[4], dd, s1v.x), fmaf(acc[5], dd, s1v.y),
                            fmaf(acc[6], dd, s1v.z), fmaf(acc[7], dd, s1v.w));
    if (!LAST) {
        ar[0] = o0;
        ar[1] = o1;
    } else {
        float4 b0 = ((const float4*)b3)[l * 2 + 0];
        float4 b1 = ((const float4*)b3)[l * 2 + 1];
        o0.x = fmaxf(o0.x + b0.x, 0.f); o0.y = fmaxf(o0.y + b0.y, 0.f);
        o0.z = fmaxf(o0.z + b0.z, 0.f); o0.w = fmaxf(o0.w + b0.w, 0.f);
        o1.x = fmaxf(o1.x + b1.x, 0.f); o1.y = fmaxf(o1.y + b1.y, 0.f);
        o1.z = fmaxf(o1.z + b1.z, 0.f); o1.w = fmaxf(o1.w + b1.w, 0.f);
        int g = batch[d];
        red_add_v4(g_sums + (size_t)g * F + l * 8, o0);
        red_add_v4(g_sums + (size_t)g * F + l * 8 + 4, o1);
        if (l == 0) atomicAdd(&g_cnt[g], 1.0f);
    }
}

// out[g] = (sums[g] . Wl) / max(cnt,1) + bl
__global__ void final_kernel(const float* __restrict__ Wl, const float* __restrict__ bl,
                             float* __restrict__ out) {
    int g = threadIdx.x;
    float c = fmaxf(g_cnt[g], 1.0f);
    float acc = 0.f;
#pragma unroll
    for (int f = 0; f < F; ++f) acc = fmaf(g_sums[g * F + f], Wl[f], acc);
    out[g] = acc / c + bl[0];
}

// ---------------- launch ----------------
extern "C" void kernel_launch(void* const* d_in, const int* in_sizes, int n_in,
                              void* d_out, int out_size) {
    const float* x   = (const float*)d_in[0];
    const int* src   = (const int*)d_in[1];
    const int* dst   = (const int*)d_in[2];
    const int* batch = (const int*)d_in[3];
    const float* W1 = (const float*)d_in[4];
    const float* b1 = (const float*)d_in[5];
    const float* W2 = (const float*)d_in[6];
    const float* b2 = (const float*)d_in[7];
    const float* W3 = (const float*)d_in[8];
    const float* b3 = (const float*)d_in[9];
    const float* Wl = (const float*)d_in[10];
    const float* bl = (const float*)d_in[11];
    float* out = (float*)d_out;

    const int NB_EDGE = (NE + 255) / 256;        // 3125
    const int NB_GEMM = (NN + 63) / 64;          // 782
    const int NB_AGG  = (NN * 8 + 255) / 256;    // 1563
    const int NB_ZERO = (NG * F + 255) / 256;    // 64

    void* cur_ptr = nullptr;
    cudaGetSymbolAddress(&cur_ptr, g_cursor4);
    cudaMemsetAsync(cur_ptr, 0, NN * 4 * sizeof(int));

    zero_kernel<<<NB_ZERO, 256>>>();
    scatter_kernel<<<NB_EDGE, 256>>>(src, dst);

    // layer 1
    gemm_tc_kernel<true><<<NB_GEMM, 128>>>(x, W1, nullptr);
    agg_kernel<false><<<NB_AGG, 256>>>(batch, b3);
    // layer 2
    gemm_tc_kernel<false><<<NB_GEMM, 128>>>(nullptr, W2, b1);
    agg_kernel<false><<<NB_AGG, 256>>>(batch, b3);
    // layer 3 (+ fused pool)
    gemm_tc_kernel<false><<<NB_GEMM, 128>>>(nullptr, W3, b2);
    agg_kernel<true><<<NB_AGG, 256>>>(batch, b3);

    final_kernel<<<1, 256>>>(Wl, bl, out);
}

// round 15
// speedup vs baseline: 1.0324x; 1.0324x over previous
#include <cuda_runtime.h>
#include <cuda_fp16.h>

#define NN 50000
#define NE 800000
#define NG 256
#define F  64

// ---------------- scratch ----------------
__device__ __align__(16) __half g_hh[NN * F];   // h * dinv[src], fp16 (gather payload)
__device__ __align__(16) float g_agg[NN * F];   // self-loop init, then full agg (fp32)
__device__ __align__(16) float g_sums[NG * F];
__device__ float g_cnt[NG];
__device__ float g_dinv[NN];
__device__ float g_invdeg[NN];
__device__ int   g_deg[NN];                     // total degree (agg row length)
__device__ __align__(16) int g_deg4[NN * 4];    // 4-sharded degree histogram
__device__ int   g_rowstart[NN];
__device__ int   g_cursor4[NN * 4];             // 4-sharded scatter cursors
__device__ int   g_counter;
__device__ int   g_ssorted[NE];                 // compact CSR (L2-resident)

__device__ __forceinline__ void red_add_v4(float* p, float4 v) {
    asm volatile("red.global.add.v4.f32 [%0], {%1, %2, %3, %4};"
                 :: "l"(p), "f"(v.x), "f"(v.y), "f"(v.z), "f"(v.w) : "memory");
}

// ---------------- prep kernels (R13 structure) ----------------
__global__ void zero_kernel() {
    int i = blockIdx.x * blockDim.x + threadIdx.x;
    if (i < NN * 4) g_deg4[i] = 0;
    if (i < NG * F) g_sums[i] = 0.0f;
    if (i < NG) g_cnt[i] = 0.0f;
    if (i == 0) g_counter = 0;
}

__global__ void deg_kernel(const int* __restrict__ dst) {
    int e = blockIdx.x * blockDim.x + threadIdx.x;
    if (e < NE) atomicAdd(&g_deg4[dst[e] * 4 + (e & 3)], 1);
}

// Fused: dinv/invdeg/cnt + block-local scan + block-atomic region placement
// + per-shard cursor init (shard sub-ranges contiguous within each row).
__global__ void scan_fused_kernel(const int* __restrict__ batch) {
    __shared__ int s[2][256];
    __shared__ int blockoff;
    int tid = threadIdx.x;
    int i = blockIdx.x * 256 + tid;
    int4 dsh = make_int4(0, 0, 0, 0);
    int v = 0;
    if (i < NN) {
        dsh = ((const int4*)g_deg4)[i];
        v = dsh.x + dsh.y + dsh.z + dsh.w;
        g_deg[i] = v;
        float d = (float)(v + 1);
        g_dinv[i] = rsqrtf(d);
        g_invdeg[i] = 1.0f / d;
        atomicAdd(&g_cnt[batch[i]], 1.0f);
    }
    s[0][tid] = v;
    __syncthreads();
    int cur = 0;
#pragma unroll
    for (int off = 1; off < 256; off <<= 1) {
        int val = s[cur][tid];
        if (tid >= off) val += s[cur][tid - off];
        s[cur ^ 1][tid] = val;
        cur ^= 1;
        __syncthreads();
    }
    if (tid == 0) blockoff = atomicAdd(&g_counter, s[cur][255]);
    __syncthreads();
    int excl = (tid == 0) ? 0 : s[cur][tid - 1];
    if (i < NN) {
        int rs = excl + blockoff;
        g_rowstart[i] = rs;
        int4 c;
        c.x = rs;
        c.y = rs + dsh.x;
        c.z = rs + dsh.x + dsh.y;
        c.w = rs + dsh.x + dsh.y + dsh.z;
        ((int4*)g_cursor4)[i] = c;
    }
}

__global__ void scatter_kernel(const int* __restrict__ src, const int* __restrict__ dst) {
    int e = blockIdx.x * blockDim.x + threadIdx.x;
    if (e < NE) {
        int d = dst[e];
        int pos = atomicAdd(&g_cursor4[d * 4 + (e & 3)], 1);
        g_ssorted[pos] = src[e];
    }
}

// ---------------- Tensor-core GEMM + self-loop init ----------------
#define XS_STRIDE 66

template <bool FIRST>
__global__ __launch_bounds__(128) void gemm_tc_kernel(const float* __restrict__ x,
                                                      const float* __restrict__ W,
                                                      const float* __restrict__ bprev) {
    __shared__ __half Wt[F * XS_STRIDE];        // Wt[n][k] = W[k][n]
    __shared__ __half Xs[4][16 * XS_STRIDE];

    int tid = threadIdx.x;
    for (int i = tid; i < F * F; i += 128) {
        int k = i >> 6, n = i & 63;
        Wt[n * XS_STRIDE + k] = __float2half(W[i]);
    }

    int warp = tid >> 5, lane = tid & 31;
    int gid = lane >> 2, tig = lane & 3;
    int nodebase = blockIdx.x * 64 + warp * 16;

    const float4* in4 = FIRST ? (const float4*)x : (const float4*)g_agg;
    const float4* b4 = (const float4*)bprev;
    int hl = lane >> 4;
    int qi = lane & 15;
    __half* Xw = Xs[warp];
#pragma unroll
    for (int rr = 0; rr < 8; ++rr) {
        int r = rr * 2 + hl;
        int node = nodebase + r;
        float4 xv = make_float4(0.f, 0.f, 0.f, 0.f);
        if (node < NN) {
            xv = in4[(size_t)node * 16 + qi];
            if (!FIRST) {
                float4 bv = b4[qi];
                xv.x = fmaxf(xv.x + bv.x, 0.f);
                xv.y = fmaxf(xv.y + bv.y, 0.f);
                xv.z = fmaxf(xv.z + bv.z, 0.f);
                xv.w = fmaxf(xv.w + bv.w, 0.f);
            }
        }
        __half2* p = (__half2*)&Xw[r * XS_STRIDE + qi * 4];
        p[0] = __floats2half2_rn(xv.x, xv.y);
        p[1] = __floats2half2_rn(xv.z, xv.w);
    }
    __syncthreads();

    unsigned a[4][4];
#pragma unroll
    for (int kt = 0; kt < 4; ++kt) {
        int kc = kt * 16 + tig * 2;
        a[kt][0] = *(const unsigned*)&Xw[gid * XS_STRIDE + kc];
        a[kt][1] = *(const unsigned*)&Xw[(gid + 8) * XS_STRIDE + kc];
        a[kt][2] = *(const unsigned*)&Xw[gid * XS_STRIDE + kc + 8];
        a[kt][3] = *(const unsigned*)&Xw[(gid + 8) * XS_STRIDE + kc + 8];
    }

    int row0 = nodebase + gid;
    int row1 = nodebase + gid + 8;
    float dv0 = 0.f, id0 = 0.f, dv1 = 0.f, id1 = 0.f;
    if (row0 < NN) { dv0 = g_dinv[row0]; id0 = g_invdeg[row0]; }
    if (row1 < NN) { dv1 = g_dinv[row1]; id1 = g_invdeg[row1]; }

#pragma unroll
    for (int nt = 0; nt < 8; ++nt) {
        float c0 = 0.f, c1 = 0.f, c2 = 0.f, c3 = 0.f;
        const __half* Wn = &Wt[(nt * 8 + gid) * XS_STRIDE];
#pragma unroll
        for (int kt = 0; kt < 4; ++kt) {
            int kc = kt * 16 + tig * 2;
            unsigned b0 = *(const unsigned*)&Wn[kc];
            unsigned b1 = *(const unsigned*)&Wn[kc + 8];
            asm volatile(
                "mma.sync.aligned.m16n8k16.row.col.f32.f16.f16.f32 "
                "{%0,%1,%2,%3}, {%4,%5,%6,%7}, {%8,%9}, {%0,%1,%2,%3};"
                : "+f"(c0), "+f"(c1), "+f"(c2), "+f"(c3)
                : "r"(a[kt][0]), "r"(a[kt][1]), "r"(a[kt][2]), "r"(a[kt][3]),
                  "r"(b0), "r"(b1));
        }
        int col = nt * 8 + tig * 2;
        if (row0 < NN) {
            *(__half2*)&g_hh[(size_t)row0 * F + col] = __floats2half2_rn(c0 * dv0, c1 * dv0);
            *(float2*)&g_agg[(size_t)row0 * F + col] = make_float2(c0 * id0, c1 * id0);
        }
        if (row1 < NN) {
            *(__half2*)&g_hh[(size_t)row1 * F + col] = __floats2half2_rn(c2 * dv1, c3 * dv1);
            *(float2*)&g_agg[(size_t)row1 * F + col] = make_float2(c2 * id1, c3 * id1);
        }
    }
}

// ---------------- CSR aggregation: 8-lane group per dst ----------------
// half2 tree accumulation (fewer issue slots) + unroll 8 (deeper MLP).
template <bool LAST>
__global__ __launch_bounds__(256) void agg_kernel(const int* __restrict__ batch,
                                                  const float* __restrict__ b3) {
    int t = blockIdx.x * blockDim.x + threadIdx.x;
    int d = t >> 3;
    int l = t & 7;
    if (d >= NN) return;
    int start = g_rowstart[d];
    int n = g_deg[d];
    const uint4* h4 = (const uint4*)g_hh;
    const int* ss = g_ssorted + start;

    float acc[8];
#pragma unroll
    for (int j = 0; j < 8; ++j) acc[j] = 0.f;

    int i = 0;
    // main: 8 edges per iteration, half2 tree reduce, one fp32 flush per slot
    for (; i + 8 <= n; i += 8) {
        uint4 r0 = h4[(size_t)ss[i + 0] * 8 + l];
        uint4 r1 = h4[(size_t)ss[i + 1] * 8 + l];
        uint4 r2 = h4[(size_t)ss[i + 2] * 8 + l];
        uint4 r3 = h4[(size_t)ss[i + 3] * 8 + l];
        uint4 r4 = h4[(size_t)ss[i + 4] * 8 + l];
        uint4 r5 = h4[(size_t)ss[i + 5] * 8 + l];
        uint4 r6 = h4[(size_t)ss[i + 6] * 8 + l];
        uint4 r7 = h4[(size_t)ss[i + 7] * 8 + l];
        const __half2* p0 = (const __half2*)&r0;
        const __half2* p1 = (const __half2*)&r1;
        const __half2* p2 = (const __half2*)&r2;
        const __half2* p3 = (const __half2*)&r3;
        const __half2* p4 = (const __half2*)&r4;
        const __half2* p5 = (const __half2*)&r5;
        const __half2* p6 = (const __half2*)&r6;
        const __half2* p7 = (const __half2*)&r7;
#pragma unroll
        for (int j = 0; j < 4; ++j) {
            __half2 t01 = __hadd2(p0[j], p1[j]);
            __half2 t23 = __hadd2(p2[j], p3[j]);
            __half2 t45 = __hadd2(p4[j], p5[j]);
            __half2 t67 = __hadd2(p6[j], p7[j]);
            __half2 ta = __hadd2(t01, t23);
            __half2 tb = __hadd2(t45, t67);
            float2 fa = __half22float2(ta);
            float2 fb = __half22float2(tb);
            acc[j * 2 + 0] += fa.x + fb.x;
            acc[j * 2 + 1] += fa.y + fb.y;
        }
    }
    // 4-edge tail
    for (; i + 4 <= n; i += 4) {
        uint4 r0 = h4[(size_t)ss[i + 0] * 8 + l];
        uint4 r1 = h4[(size_t)ss[i + 1] * 8 + l];
        uint4 r2 = h4[(size_t)ss[i + 2] * 8 + l];
        uint4 r3 = h4[(size_t)ss[i + 3] * 8 + l];
        const __half2* p0 = (const __half2*)&r0;
        const __half2* p1 = (const __half2*)&r1;
        const __half2* p2 = (const __half2*)&r2;
        const __half2* p3 = (const __half2*)&r3;
#pragma unroll
        for (int j = 0; j < 4; ++j) {
            __half2 t01 = __hadd2(p0[j], p1[j]);
            __half2 t23 = __hadd2(p2[j], p3[j]);
            float2 fa = __half22float2(t01);
            float2 fb = __half22float2(t23);
            acc[j * 2 + 0] += fa.x + fb.x;
            acc[j * 2 + 1] += fa.y + fb.y;
        }
    }
    // scalar tail (fp32 adds)
    for (; i < n; ++i) {
        uint4 r0 = h4[(size_t)ss[i] * 8 + l];
        const __half2* p0 = (const __half2*)&r0;
#pragma unroll
        for (int j = 0; j < 4; ++j) {
            float2 f0 = __half22float2(p0[j]);
            acc[j * 2 + 0] += f0.x;
            acc[j * 2 + 1] += f0.y;
        }
    }

    float dd = g_dinv[d];
    float4* ar = (float4*)(g_agg + (size_t)d * F + l * 8);
    float4 s0v = ar[0];
    float4 s1v = ar[1];
    float4 o0 = make_float4(fmaf(acc[0], dd, s0v.x), fmaf(acc[1], dd, s0v.y),
                            fmaf(acc[2], dd, s0v.z), fmaf(acc[3], dd, s0v.w));
    float4 o1 = make_float4(fmaf(acc[4], dd, s1v.x), fmaf(acc[5], dd, s1v.y),
                            fmaf(acc[6], dd, s1v.z), fmaf(acc[7], dd, s1v.w));
    if (!LAST) {
        ar[0] = o0;
        ar[1] = o1;
    } else {
        float4 b0 = ((const float4*)b3)[l * 2 + 0];
        float4 b1 = ((const float4*)b3)[l * 2 + 1];
        o0.x = fmaxf(o0.x + b0.x, 0.f); o0.y = fmaxf(o0.y + b0.y, 0.f);
        o0.z = fmaxf(o0.z + b0.z, 0.f); o0.w = fmaxf(o0.w + b0.w, 0.f);
        o1.x = fmaxf(o1.x + b1.x, 0.f); o1.y = fmaxf(o1.y + b1.y, 0.f);
        o1.z = fmaxf(o1.z + b1.z, 0.f); o1.w = fmaxf(o1.w + b1.w, 0.f);
        int g = batch[d];
        red_add_v4(g_sums + (size_t)g * F + l * 8, o0);
        red_add_v4(g_sums + (size_t)g * F + l * 8 + 4, o1);
    }
}

// out[g] = (sums[g] . Wl) / max(cnt,1) + bl
__global__ void final_kernel(const float* __restrict__ Wl, const float* __restrict__ bl,
                             float* __restrict__ out) {
    int g = threadIdx.x;
    float c = fmaxf(g_cnt[g], 1.0f);
    float acc = 0.f;
#pragma unroll
    for (int f = 0; f < F; ++f) acc = fmaf(g_sums[g * F + f], Wl[f], acc);
    out[g] = acc / c + bl[0];
}

// ---------------- launch ----------------
extern "C" void kernel_launch(void* const* d_in, const int* in_sizes, int n_in,
                              void* d_out, int out_size) {
    const float* x   = (const float*)d_in[0];
    const int* src   = (const int*)d_in[1];
    const int* dst   = (const int*)d_in[2];
    const int* batch = (const int*)d_in[3];
    const float* W1 = (const float*)d_in[4];
    const float* b1 = (const float*)d_in[5];
    const float* W2 = (const float*)d_in[6];
    const float* b2 = (const float*)d_in[7];
    const float* W3 = (const float*)d_in[8];
    const float* b3 = (const float*)d_in[9];
    const float* Wl = (const float*)d_in[10];
    const float* bl = (const float*)d_in[11];
    float* out = (float*)d_out;

    const int NB_NODE = (NN + 255) / 256;        // 196
    const int NB_EDGE = (NE + 255) / 256;        // 3125
    const int NB_GEMM = (NN + 63) / 64;          // 782
    const int NB_AGG  = (NN * 8 + 255) / 256;    // 1563
    const int NB_ZERO = (NN * 4 + 255) / 256;    // 782

    zero_kernel<<<NB_ZERO, 256>>>();
    deg_kernel<<<NB_EDGE, 256>>>(dst);
    scan_fused_kernel<<<NB_NODE, 256>>>(batch);
    scatter_kernel<<<NB_EDGE, 256>>>(src, dst);

    // layer 1
    gemm_tc_kernel<true><<<NB_GEMM, 128>>>(x, W1, nullptr);
    agg_kernel<false><<<NB_AGG, 256>>>(batch, b3);
    // layer 2
    gemm_tc_kernel<false><<<NB_GEMM, 128>>>(nullptr, W2, b1);
    agg_kernel<false><<<NB_AGG, 256>>>(batch, b3);
    // layer 3 (+ fused pool)
    gemm_tc_kernel<false><<<NB_GEMM, 128>>>(nullptr, W3, b2);
    agg_kernel<true><<<NB_AGG, 256>>>(batch, b3);

    final_kernel<<<1, 256>>>(Wl, bl, out);
}

// round 16
// speedup vs baseline: 1.0896x; 1.0554x over previous
#include <cuda_runtime.h>
#include <cuda_fp16.h>

#define NN 50000
#define NE 800000
#define NG 256
#define F  64
#define XS_STRIDE 66

// ---------------- scratch ----------------
__device__ __align__(16) __half g_hh0[NN * F];  // ping
__device__ __align__(16) __half g_hh1[NN * F];  // pong
__device__ __align__(16) float g_agg[NN * F];   // self-loop term (invdeg-scaled h)
__device__ __align__(16) float g_sums[NG * F];
__device__ float g_cnt[NG];
__device__ float g_dinv[NN];
__device__ float g_invdeg[NN];
__device__ int   g_deg[NN];
__device__ __align__(16) int g_deg4[NN * 4];
__device__ int   g_rowstart[NN];
__device__ int   g_cursor4[NN * 4];
__device__ int   g_counter;
__device__ int   g_ssorted[NE];

__device__ __forceinline__ void red_add_v4(float* p, float4 v) {
    asm volatile("red.global.add.v4.f32 [%0], {%1, %2, %3, %4};"
                 :: "l"(p), "f"(v.x), "f"(v.y), "f"(v.z), "f"(v.w) : "memory");
}

// gather-accumulate one node's neighbor sum over 8 fp32 slots (lane l owns 16B)
__device__ __forceinline__ void gather_row(const __half* __restrict__ hh,
                                           const int* __restrict__ ss, int n, int l,
                                           float* acc) {
    const uint4* h4 = (const uint4*)hh;
    int i = 0;
    for (; i + 8 <= n; i += 8) {
        uint4 r0 = h4[(size_t)ss[i + 0] * 8 + l];
        uint4 r1 = h4[(size_t)ss[i + 1] * 8 + l];
        uint4 r2 = h4[(size_t)ss[i + 2] * 8 + l];
        uint4 r3 = h4[(size_t)ss[i + 3] * 8 + l];
        uint4 r4 = h4[(size_t)ss[i + 4] * 8 + l];
        uint4 r5 = h4[(size_t)ss[i + 5] * 8 + l];
        uint4 r6 = h4[(size_t)ss[i + 6] * 8 + l];
        uint4 r7 = h4[(size_t)ss[i + 7] * 8 + l];
        const __half2* p0 = (const __half2*)&r0;
        const __half2* p1 = (const __half2*)&r1;
        const __half2* p2 = (const __half2*)&r2;
        const __half2* p3 = (const __half2*)&r3;
        const __half2* p4 = (const __half2*)&r4;
        const __half2* p5 = (const __half2*)&r5;
        const __half2* p6 = (const __half2*)&r6;
        const __half2* p7 = (const __half2*)&r7;
#pragma unroll
        for (int j = 0; j < 4; ++j) {
            __half2 t01 = __hadd2(p0[j], p1[j]);
            __half2 t23 = __hadd2(p2[j], p3[j]);
            __half2 t45 = __hadd2(p4[j], p5[j]);
            __half2 t67 = __hadd2(p6[j], p7[j]);
            __half2 ta = __hadd2(t01, t23);
            __half2 tb = __hadd2(t45, t67);
            float2 fa = __half22float2(ta);
            float2 fb = __half22float2(tb);
            acc[j * 2 + 0] += fa.x + fb.x;
            acc[j * 2 + 1] += fa.y + fb.y;
        }
    }
    for (; i + 4 <= n; i += 4) {
        uint4 r0 = h4[(size_t)ss[i + 0] * 8 + l];
        uint4 r1 = h4[(size_t)ss[i + 1] * 8 + l];
        uint4 r2 = h4[(size_t)ss[i + 2] * 8 + l];
        uint4 r3 = h4[(size_t)ss[i + 3] * 8 + l];
        const __half2* p0 = (const __half2*)&r0;
        const __half2* p1 = (const __half2*)&r1;
        const __half2* p2 = (const __half2*)&r2;
        const __half2* p3 = (const __half2*)&r3;
#pragma unroll
        for (int j = 0; j < 4; ++j) {
            __half2 t01 = __hadd2(p0[j], p1[j]);
            __half2 t23 = __hadd2(p2[j], p3[j]);
            float2 fa = __half22float2(t01);
            float2 fb = __half22float2(t23);
            acc[j * 2 + 0] += fa.x + fb.x;
            acc[j * 2 + 1] += fa.y + fb.y;
        }
    }
    for (; i < n; ++i) {
        uint4 r0 = h4[(size_t)ss[i] * 8 + l];
        const __half2* p0 = (const __half2*)&r0;
#pragma unroll
        for (int j = 0; j < 4; ++j) {
            float2 f0 = __half22float2(p0[j]);
            acc[j * 2 + 0] += f0.x;
            acc[j * 2 + 1] += f0.y;
        }
    }
}

// ---------------- prep kernels ----------------
__global__ void zero_kernel() {
    int i = blockIdx.x * blockDim.x + threadIdx.x;
    if (i < NN * 4) g_deg4[i] = 0;
    if (i < NG * F) g_sums[i] = 0.0f;
    if (i < NG) g_cnt[i] = 0.0f;
    if (i == 0) g_counter = 0;
}

__global__ void deg_kernel(const int* __restrict__ dst) {
    int e = blockIdx.x * blockDim.x + threadIdx.x;
    if (e < NE) atomicAdd(&g_deg4[dst[e] * 4 + (e & 3)], 1);
}

__global__ void scan_fused_kernel(const int* __restrict__ batch) {
    __shared__ int s[2][256];
    __shared__ int blockoff;
    int tid = threadIdx.x;
    int i = blockIdx.x * 256 + tid;
    int4 dsh = make_int4(0, 0, 0, 0);
    int v = 0;
    if (i < NN) {
        dsh = ((const int4*)g_deg4)[i];
        v = dsh.x + dsh.y + dsh.z + dsh.w;
        g_deg[i] = v;
        float d = (float)(v + 1);
        g_dinv[i] = rsqrtf(d);
        g_invdeg[i] = 1.0f / d;
        atomicAdd(&g_cnt[batch[i]], 1.0f);
    }
    s[0][tid] = v;
    __syncthreads();
    int cur = 0;
#pragma unroll
    for (int off = 1; off < 256; off <<= 1) {
        int val = s[cur][tid];
        if (tid >= off) val += s[cur][tid - off];
        s[cur ^ 1][tid] = val;
        cur ^= 1;
        __syncthreads();
    }
    if (tid == 0) blockoff = atomicAdd(&g_counter, s[cur][255]);
    __syncthreads();
    int excl = (tid == 0) ? 0 : s[cur][tid - 1];
    if (i < NN) {
        int rs = excl + blockoff;
        g_rowstart[i] = rs;
        int4 c;
        c.x = rs;
        c.y = rs + dsh.x;
        c.z = rs + dsh.x + dsh.y;
        c.w = rs + dsh.x + dsh.y + dsh.z;
        ((int4*)g_cursor4)[i] = c;
    }
}

__global__ void scatter_kernel(const int* __restrict__ src, const int* __restrict__ dst) {
    int e = blockIdx.x * blockDim.x + threadIdx.x;
    if (e < NE) {
        int d = dst[e];
        int pos = atomicAdd(&g_cursor4[d * 4 + (e & 3)], 1);
        g_ssorted[pos] = src[e];
    }
}

// ---------------- layer-1 tensor-core GEMM (x @ W1) ----------------
__global__ __launch_bounds__(128) void gemm1_kernel(const float* __restrict__ x,
                                                    const float* __restrict__ W,
                                                    __half* __restrict__ hh_out) {
    __shared__ __half Wt[F * XS_STRIDE];
    __shared__ __half Xs[4][16 * XS_STRIDE];

    int tid = threadIdx.x;
    for (int i = tid; i < F * F; i += 128) {
        int k = i >> 6, n = i & 63;
        Wt[n * XS_STRIDE + k] = __float2half(W[i]);
    }

    int warp = tid >> 5, lane = tid & 31;
    int gid = lane >> 2, tig = lane & 3;
    int nodebase = blockIdx.x * 64 + warp * 16;

    const float4* in4 = (const float4*)x;
    int hl = lane >> 4;
    int qi = lane & 15;
    __half* Xw = Xs[warp];
#pragma unroll
    for (int rr = 0; rr < 8; ++rr) {
        int r = rr * 2 + hl;
        int node = nodebase + r;
        float4 xv = make_float4(0.f, 0.f, 0.f, 0.f);
        if (node < NN) xv = in4[(size_t)node * 16 + qi];
        __half2* p = (__half2*)&Xw[r * XS_STRIDE + qi * 4];
        p[0] = __floats2half2_rn(xv.x, xv.y);
        p[1] = __floats2half2_rn(xv.z, xv.w);
    }
    __syncthreads();

    unsigned a[4][4];
#pragma unroll
    for (int kt = 0; kt < 4; ++kt) {
        int kc = kt * 16 + tig * 2;
        a[kt][0] = *(const unsigned*)&Xw[gid * XS_STRIDE + kc];
        a[kt][1] = *(const unsigned*)&Xw[(gid + 8) * XS_STRIDE + kc];
        a[kt][2] = *(const unsigned*)&Xw[gid * XS_STRIDE + kc + 8];
        a[kt][3] = *(const unsigned*)&Xw[(gid + 8) * XS_STRIDE + kc + 8];
    }

    int row0 = nodebase + gid;
    int row1 = nodebase + gid + 8;
    float dv0 = 0.f, id0 = 0.f, dv1 = 0.f, id1 = 0.f;
    if (row0 < NN) { dv0 = g_dinv[row0]; id0 = g_invdeg[row0]; }
    if (row1 < NN) { dv1 = g_dinv[row1]; id1 = g_invdeg[row1]; }

#pragma unroll
    for (int nt = 0; nt < 8; ++nt) {
        float c0 = 0.f, c1 = 0.f, c2 = 0.f, c3 = 0.f;
        const __half* Wn = &Wt[(nt * 8 + gid) * XS_STRIDE];
#pragma unroll
        for (int kt = 0; kt < 4; ++kt) {
            int kc = kt * 16 + tig * 2;
            unsigned b0 = *(const unsigned*)&Wn[kc];
            unsigned b1 = *(const unsigned*)&Wn[kc + 8];
            asm volatile(
                "mma.sync.aligned.m16n8k16.row.col.f32.f16.f16.f32 "
                "{%0,%1,%2,%3}, {%4,%5,%6,%7}, {%8,%9}, {%0,%1,%2,%3};"
                : "+f"(c0), "+f"(c1), "+f"(c2), "+f"(c3)
                : "r"(a[kt][0]), "r"(a[kt][1]), "r"(a[kt][2]), "r"(a[kt][3]),
                  "r"(b0), "r"(b1));
        }
        int col = nt * 8 + tig * 2;
        if (row0 < NN) {
            *(__half2*)&hh_out[(size_t)row0 * F + col] = __floats2half2_rn(c0 * dv0, c1 * dv0);
            *(float2*)&g_agg[(size_t)row0 * F + col] = make_float2(c0 * id0, c1 * id0);
        }
        if (row1 < NN) {
            *(__half2*)&hh_out[(size_t)row1 * F + col] = __floats2half2_rn(c2 * dv1, c3 * dv1);
            *(float2*)&g_agg[(size_t)row1 * F + col] = make_float2(c2 * id1, c3 * id1);
        }
    }
}

// ---------------- fused agg(L) + gemm(L+1) ----------------
// Block: 256 threads, 32 nodes. Phase 1: agg (8 lanes/node), relu(out+b) -> smem fp16.
// Phase 2: warps 0-1 MMA (16 nodes each), write hh_out (dinv) + g_agg (invdeg).
__global__ __launch_bounds__(256) void fused_agg_gemm_kernel(
    const __half* __restrict__ hh_in, __half* __restrict__ hh_out,
    const float* __restrict__ W, const float* __restrict__ bprev) {
    __shared__ __half Wt[F * XS_STRIDE];
    __shared__ __half Xs[32 * XS_STRIDE];

    int tid = threadIdx.x;
    for (int i = tid; i < F * F; i += 256) {
        int k = i >> 6, n = i & 63;
        Wt[n * XS_STRIDE + k] = __float2half(W[i]);
    }

    // phase 1: aggregation for 32 nodes
    int ln = tid >> 3;
    int l = tid & 7;
    int d = blockIdx.x * 32 + ln;

    float o[8];
#pragma unroll
    for (int j = 0; j < 8; ++j) o[j] = 0.f;

    if (d < NN) {
        gather_row(hh_in, g_ssorted + g_rowstart[d], g_deg[d], l, o);
        float dd = g_dinv[d];
        const float4* ar = (const float4*)(g_agg + (size_t)d * F + l * 8);
        float4 s0v = ar[0];
        float4 s1v = ar[1];
        float4 b0 = ((const float4*)bprev)[l * 2 + 0];
        float4 b1 = ((const float4*)bprev)[l * 2 + 1];
        o[0] = fmaxf(fmaf(o[0], dd, s0v.x) + b0.x, 0.f);
        o[1] = fmaxf(fmaf(o[1], dd, s0v.y) + b0.y, 0.f);
        o[2] = fmaxf(fmaf(o[2], dd, s0v.z) + b0.z, 0.f);
        o[3] = fmaxf(fmaf(o[3], dd, s0v.w) + b0.w, 0.f);
        o[4] = fmaxf(fmaf(o[4], dd, s1v.x) + b1.x, 0.f);
        o[5] = fmaxf(fmaf(o[5], dd, s1v.y) + b1.y, 0.f);
        o[6] = fmaxf(fmaf(o[6], dd, s1v.z) + b1.z, 0.f);
        o[7] = fmaxf(fmaf(o[7], dd, s1v.w) + b1.w, 0.f);
    }
    __half2* xp = (__half2*)&Xs[ln * XS_STRIDE + l * 8];
    xp[0] = __floats2half2_rn(o[0], o[1]);
    xp[1] = __floats2half2_rn(o[2], o[3]);
    xp[2] = __floats2half2_rn(o[4], o[5]);
    xp[3] = __floats2half2_rn(o[6], o[7]);
    __syncthreads();

    // phase 2: MMA on warps 0-1 (16 nodes each)
    int warp = tid >> 5, lane = tid & 31;
    if (warp >= 2) return;
    int gid = lane >> 2, tig = lane & 3;
    const __half* Xw = &Xs[warp * 16 * XS_STRIDE];

    unsigned a[4][4];
#pragma unroll
    for (int kt = 0; kt < 4; ++kt) {
        int kc = kt * 16 + tig * 2;
        a[kt][0] = *(const unsigned*)&Xw[gid * XS_STRIDE + kc];
        a[kt][1] = *(const unsigned*)&Xw[(gid + 8) * XS_STRIDE + kc];
        a[kt][2] = *(const unsigned*)&Xw[gid * XS_STRIDE + kc + 8];
        a[kt][3] = *(const unsigned*)&Xw[(gid + 8) * XS_STRIDE + kc + 8];
    }

    int row0 = blockIdx.x * 32 + warp * 16 + gid;
    int row1 = row0 + 8;
    float dv0 = 0.f, id0 = 0.f, dv1 = 0.f, id1 = 0.f;
    if (row0 < NN) { dv0 = g_dinv[row0]; id0 = g_invdeg[row0]; }
    if (row1 < NN) { dv1 = g_dinv[row1]; id1 = g_invdeg[row1]; }

#pragma unroll
    for (int nt = 0; nt < 8; ++nt) {
        float c0 = 0.f, c1 = 0.f, c2 = 0.f, c3 = 0.f;
        const __half* Wn = &Wt[(nt * 8 + gid) * XS_STRIDE];
#pragma unroll
        for (int kt = 0; kt < 4; ++kt) {
            int kc = kt * 16 + tig * 2;
            unsigned b0 = *(const unsigned*)&Wn[kc];
            unsigned b1 = *(const unsigned*)&Wn[kc + 8];
            asm volatile(
                "mma.sync.aligned.m16n8k16.row.col.f32.f16.f16.f32 "
                "{%0,%1,%2,%3}, {%4,%5,%6,%7}, {%8,%9}, {%0,%1,%2,%3};"
                : "+f"(c0), "+f"(c1), "+f"(c2), "+f"(c3)
                : "r"(a[kt][0]), "r"(a[kt][1]), "r"(a[kt][2]), "r"(a[kt][3]),
                  "r"(b0), "r"(b1));
        }
        int col = nt * 8 + tig * 2;
        if (row0 < NN) {
            *(__half2*)&hh_out[(size_t)row0 * F + col] = __floats2half2_rn(c0 * dv0, c1 * dv0);
            *(float2*)&g_agg[(size_t)row0 * F + col] = make_float2(c0 * id0, c1 * id0);
        }
        if (row1 < NN) {
            *(__half2*)&hh_out[(size_t)row1 * F + col] = __floats2half2_rn(c2 * dv1, c3 * dv1);
            *(float2*)&g_agg[(size_t)row1 * F + col] = make_float2(c2 * id1, c3 * id1);
        }
    }
}

// ---------------- last-layer aggregation + pool ----------------
__global__ __launch_bounds__(256) void agg_last_kernel(const __half* __restrict__ hh_in,
                                                       const int* __restrict__ batch,
                                                       const float* __restrict__ b3) {
    int t = blockIdx.x * blockDim.x + threadIdx.x;
    int d = t >> 3;
    int l = t & 7;
    if (d >= NN) return;

    float acc[8];
#pragma unroll
    for (int j = 0; j < 8; ++j) acc[j] = 0.f;
    gather_row(hh_in, g_ssorted + g_rowstart[d], g_deg[d], l, acc);

    float dd = g_dinv[d];
    const float4* ar = (const float4*)(g_agg + (size_t)d * F + l * 8);
    float4 s0v = ar[0];
    float4 s1v = ar[1];
    float4 b0 = ((const float4*)b3)[l * 2 + 0];
    float4 b1 = ((const float4*)b3)[l * 2 + 1];
    float4 o0 = make_float4(fmaxf(fmaf(acc[0], dd, s0v.x) + b0.x, 0.f),
                            fmaxf(fmaf(acc[1], dd, s0v.y) + b0.y, 0.f),
                            fmaxf(fmaf(acc[2], dd, s0v.z) + b0.z, 0.f),
                            fmaxf(fmaf(acc[3], dd, s0v.w) + b0.w, 0.f));
    float4 o1 = make_float4(fmaxf(fmaf(acc[4], dd, s1v.x) + b1.x, 0.f),
                            fmaxf(fmaf(acc[5], dd, s1v.y) + b1.y, 0.f),
                            fmaxf(fmaf(acc[6], dd, s1v.z) + b1.z, 0.f),
                            fmaxf(fmaf(acc[7], dd, s1v.w) + b1.w, 0.f));
    int g = batch[d];
    red_add_v4(g_sums + (size_t)g * F + l * 8, o0);
    red_add_v4(g_sums + (size_t)g * F + l * 8 + 4, o1);
}

// out[g] = (sums[g] . Wl) / max(cnt,1) + bl
__global__ void final_kernel(const float* __restrict__ Wl, const float* __restrict__ bl,
                             float* __restrict__ out) {
    int g = threadIdx.x;
    float c = fmaxf(g_cnt[g], 1.0f);
    float acc = 0.f;
#pragma unroll
    for (int f = 0; f < F; ++f) acc = fmaf(g_sums[g * F + f], Wl[f], acc);
    out[g] = acc / c + bl[0];
}

// ---------------- launch ----------------
extern "C" void kernel_launch(void* const* d_in, const int* in_sizes, int n_in,
                              void* d_out, int out_size) {
    const float* x   = (const float*)d_in[0];
    const int* src   = (const int*)d_in[1];
    const int* dst   = (const int*)d_in[2];
    const int* batch = (const int*)d_in[3];
    const float* W1 = (const float*)d_in[4];
    const float* b1 = (const float*)d_in[5];
    const float* W2 = (const float*)d_in[6];
    const float* b2 = (const float*)d_in[7];
    const float* W3 = (const float*)d_in[8];
    const float* b3 = (const float*)d_in[9];
    const float* Wl = (const float*)d_in[10];
    const float* bl = (const float*)d_in[11];
    float* out = (float*)d_out;

    const int NB_NODE = (NN + 255) / 256;        // 196
    const int NB_EDGE = (NE + 255) / 256;        // 3125
    const int NB_G1   = (NN + 63) / 64;          // 782
    const int NB_FUSE = (NN + 31) / 32;          // 1563
    const int NB_AGG  = (NN * 8 + 255) / 256;    // 1563
    const int NB_ZERO = (NN * 4 + 255) / 256;    // 782

    static __half* hhA = nullptr;
    static __half* hhB = nullptr;
    if (!hhA) {
        void* p;
        cudaGetSymbolAddress(&p, g_hh0); hhA = (__half*)p;
        cudaGetSymbolAddress(&p, g_hh1); hhB = (__half*)p;
    }

    zero_kernel<<<NB_ZERO, 256>>>();
    deg_kernel<<<NB_EDGE, 256>>>(dst);
    scan_fused_kernel<<<NB_NODE, 256>>>(batch);
    scatter_kernel<<<NB_EDGE, 256>>>(src, dst);

    // layer 1 GEMM -> hhA
    gemm1_kernel<<<NB_G1, 128>>>(x, W1, hhA);
    // agg1 + gemm2 (fused) -> hhB
    fused_agg_gemm_kernel<<<NB_FUSE, 256>>>(hhA, hhB, W2, b1);
    // agg2 + gemm3 (fused) -> hhA
    fused_agg_gemm_kernel<<<NB_FUSE, 256>>>(hhB, hhA, W3, b2);
    // agg3 + pool
    agg_last_kernel<<<NB_AGG, 256>>>(hhA, batch, b3);

    final_kernel<<<1, 256>>>(Wl, bl, out);
}